// round 2
// baseline (speedup 1.0000x reference)
#include <cuda_runtime.h>
#include <cstdint>

#define BATCH 8192
#define IND   128
#define HID   1024
#define OUTD  128
#define NW    8          // warps per CTA
#define RPW   4          // batch rows per warp (packed as 2x f32x2)
#define RPC   (NW*RPW)   // 32 rows per CTA
#define NT    (HID/32)   // 32 hidden tiles

// smem layout (floats):
//   sh  : [NW][HID] float4  -> 32768 floats (s history: 4 rows interleaved)
//   ush : [NW][IND] float4  ->  4096 floats (u rows: 4 rows interleaved)
//   stg : 8448 floats       -> BwT2 [128][33]f2 / DsT2,DwT2 [32][129]f2 (duplicated pairs)
//   bsd : 4224 floats       -> 2 x [32][33]f2 double-buffered Bs chunk (duplicated)
#define SH_OFF   0
#define USH_OFF  32768
#define STG_OFF  36864
#define BSD_OFF  45312
#define SMEM_FLOATS 49536
#define SMEM_BYTES  (SMEM_FLOATS * 4)

typedef unsigned long long ull;

__device__ __forceinline__ ull ffma2(ull a, ull b, ull c) {
    ull d;
    asm("fma.rn.f32x2 %0, %1, %2, %3;" : "=l"(d) : "l"(a), "l"(b), "l"(c));
    return d;
}
__device__ __forceinline__ ull fadd2(ull a, ull b) {
    ull d;
    asm("add.rn.f32x2 %0, %1, %2;" : "=l"(d) : "l"(a), "l"(b));
    return d;
}
__device__ __forceinline__ float2 unpack2(ull v) {
    float2 f;
    asm("mov.b64 {%0, %1}, %2;" : "=f"(f.x), "=f"(f.y) : "l"(v));
    return f;
}

__device__ __forceinline__ float fast_tanh(float x) {
    // tanh(x) = 1 - 2/(exp(2x)+1) via ex2.approx + rcp.approx (~1e-7 abs err)
    float e;
    asm("ex2.approx.f32 %0, %1;" : "=f"(e) : "f"(x * 2.8853900817779268f));
    float r;
    asm("rcp.approx.f32 %0, %1;" : "=f"(r) : "f"(e + 1.0f));
    return fmaf(-2.0f, r, 1.0f);
}

__global__ void __launch_bounds__(256, 1)
ren_kernel(const float* __restrict__ u,  const float* __restrict__ Bw,
           const float* __restrict__ Bs, const float* __restrict__ Ds,
           const float* __restrict__ Dw, float* __restrict__ out)
{
    extern __shared__ float smem[];
    ulonglong2* sh  = (ulonglong2*)(smem + SH_OFF);   // [NW][HID], 16B = 4 rows
    ulonglong2* ush = (ulonglong2*)(smem + USH_OFF);  // [NW][IND]
    ull*        stg = (ull*)(smem + STG_OFF);         // duplicated-pair staging
    ull*        bsd = (ull*)(smem + BSD_OFF);         // 2 x 1056 ull buffers

    const int tid  = threadIdx.x;
    const int warp = tid >> 5;
    const int lane = tid & 31;
    const int r0   = blockIdx.x * RPC + warp * RPW;   // rows r0..r0+3

    // stage this warp's 4 u rows (interleaved float4)
    ulonglong2* myu  = ush + warp * IND;
    ulonglong2* mysh = sh  + warp * HID;
    for (int k = lane; k < IND; k += 32) {
        float4 v = make_float4(u[(size_t)(r0+0)*IND + k], u[(size_t)(r0+1)*IND + k],
                               u[(size_t)(r0+2)*IND + k], u[(size_t)(r0+3)*IND + k]);
        ((float4*)myu)[k] = v;
    }

    for (int t = 0; t < NT; ++t) {
        const int h0 = t * 32;

        __syncthreads();
        // ---- stage BwT duplicated: stg[k*33 + c] = (Bw[(h0+c)*IND+k]) x2
        {
            const int c  = tid >> 3;
            const int kb = (tid & 7) << 4;
            const float4* src = (const float4*)(Bw + (size_t)(h0 + c)*IND + kb);
            float2* dst = (float2*)stg;
            #pragma unroll
            for (int i = 0; i < 4; ++i) {
                float4 v = src[i];
                int k = kb + 4*i;
                dst[(k+0)*33 + c] = make_float2(v.x, v.x);
                dst[(k+1)*33 + c] = make_float2(v.y, v.y);
                dst[(k+2)*33 + c] = make_float2(v.z, v.z);
                dst[(k+3)*33 + c] = make_float2(v.w, v.w);
            }
        }
        // ---- stage Bs chunk 0 into buffer 0 (duplicated)
        {
            const int c  = tid >> 3;
            const int jb = (tid & 7) << 2;
            float4 v = *(const float4*)(Bs + (size_t)(h0 + c)*HID + jb);
            float2* dst = (float2*)bsd;
            dst[(jb+0)*33 + c] = make_float2(v.x, v.x);
            dst[(jb+1)*33 + c] = make_float2(v.y, v.y);
            dst[(jb+2)*33 + c] = make_float2(v.z, v.z);
            dst[(jb+3)*33 + c] = make_float2(v.w, v.w);
        }
        __syncthreads();

        // ---- acc = B u for this tile (packed rows: acc01 = rows 0,1; acc23 = rows 2,3)
        ull a01a = 0, a01b = 0, a23a = 0, a23b = 0;
        #pragma unroll 8
        for (int k = 0; k < IND; k += 2) {
            ulonglong2 uv0 = myu[k];
            ull w0 = stg[k*33 + lane];
            ulonglong2 uv1 = myu[k+1];
            ull w1 = stg[(k+1)*33 + lane];
            a01a = ffma2(uv0.x, w0, a01a);
            a23a = ffma2(uv0.y, w0, a23a);
            a01b = ffma2(uv1.x, w1, a01b);
            a23b = ffma2(uv1.y, w1, a23b);
        }

        // ---- j-chunk sweep: history GEMM chunks, diagonal chunk last
        for (int jc = 0; jc <= t; ++jc) {
            ull* cur = bsd + (jc & 1) * 1056;

            // prefetch-stage next chunk into the other buffer (overlaps compute)
            if (jc < t) {
                float2* nxt = (float2*)(bsd + ((jc+1) & 1) * 1056);
                const int c  = tid >> 3;
                const int jb = (tid & 7) << 2;
                float4 v = *(const float4*)(Bs + (size_t)(h0 + c)*HID + (jc+1)*32 + jb);
                nxt[(jb+0)*33 + c] = make_float2(v.x, v.x);
                nxt[(jb+1)*33 + c] = make_float2(v.y, v.y);
                nxt[(jb+2)*33 + c] = make_float2(v.z, v.z);
                nxt[(jb+3)*33 + c] = make_float2(v.w, v.w);
            }

            if (jc < t) {
                const int j0 = jc * 32;
                #pragma unroll 8
                for (int j = 0; j < 32; j += 2) {
                    ulonglong2 sv0 = mysh[j0 + j];
                    ull b0 = cur[j*33 + lane];
                    ulonglong2 sv1 = mysh[j0 + j + 1];
                    ull b1 = cur[(j+1)*33 + lane];
                    a01a = ffma2(sv0.x, b0, a01a);
                    a23a = ffma2(sv0.y, b0, a23a);
                    a01b = ffma2(sv1.x, b1, a01b);
                    a23b = ffma2(sv1.y, b1, a23b);
                }
            } else {
                // ---- diagonal block: sequential sweep, strict lower triangular
                float2 a01 = unpack2(fadd2(a01a, a01b));
                float2 a23 = unpack2(fadd2(a23a, a23b));
                float s0 = 0.f, s1 = 0.f, s2 = 0.f, s3 = 0.f;
                const float2* bcol = (const float2*)cur;
                #pragma unroll
                for (int i = 0; i < 32; ++i) {
                    float t0 = fast_tanh(a01.x);
                    float t1 = fast_tanh(a01.y);
                    float t2 = fast_tanh(a23.x);
                    float t3 = fast_tanh(a23.y);
                    float v0 = __shfl_sync(0xffffffffu, t0, i);
                    float v1 = __shfl_sync(0xffffffffu, t1, i);
                    float v2 = __shfl_sync(0xffffffffu, t2, i);
                    float v3 = __shfl_sync(0xffffffffu, t3, i);
                    float b  = bcol[i*33 + lane].x;
                    if (lane > i) {
                        a01.x = fmaf(b, v0, a01.x);
                        a01.y = fmaf(b, v1, a01.y);
                        a23.x = fmaf(b, v2, a23.x);
                        a23.y = fmaf(b, v3, a23.y);
                    }
                    if (lane == i) { s0 = t0; s1 = t1; s2 = t2; s3 = t3; }
                }
                ((float4*)mysh)[h0 + lane] = make_float4(s0, s1, s2, s3);
            }
            __syncthreads();
        }
    }

    // ---- output GEMM: y = s @ Ds^T + u @ Dw^T (s never leaves SMEM)
    ull o01[4] = {0,0,0,0};
    ull o23[4] = {0,0,0,0};

    for (int jc = 0; jc < NT; ++jc) {
        const int j0 = jc * 32;
        __syncthreads();
        {
            // stage DsT duplicated: stg[j*129 + o] = (Ds[o*HID + j0 + j]) x2
            const int o  = tid >> 1;
            const int jb = (tid & 1) << 4;
            const float4* src = (const float4*)(Ds + (size_t)o*HID + j0 + jb);
            float2* dst = (float2*)stg;
            #pragma unroll
            for (int i = 0; i < 4; ++i) {
                float4 v = src[i];
                int j = jb + 4*i;
                dst[(j+0)*129 + o] = make_float2(v.x, v.x);
                dst[(j+1)*129 + o] = make_float2(v.y, v.y);
                dst[(j+2)*129 + o] = make_float2(v.z, v.z);
                dst[(j+3)*129 + o] = make_float2(v.w, v.w);
            }
        }
        __syncthreads();
        #pragma unroll 4
        for (int j = 0; j < 32; ++j) {
            ulonglong2 sv = mysh[j0 + j];
            #pragma unroll
            for (int g = 0; g < 4; ++g) {
                ull d = stg[j*129 + lane + 32*g];
                o01[g] = ffma2(sv.x, d, o01[g]);
                o23[g] = ffma2(sv.y, d, o23[g]);
            }
        }
    }

    for (int kc = 0; kc < IND/32; ++kc) {
        const int k0 = kc * 32;
        __syncthreads();
        {
            const int o  = tid >> 1;
            const int kb = (tid & 1) << 4;
            const float4* src = (const float4*)(Dw + (size_t)o*IND + k0 + kb);
            float2* dst = (float2*)stg;
            #pragma unroll
            for (int i = 0; i < 4; ++i) {
                float4 v = src[i];
                int k = kb + 4*i;
                dst[(k+0)*129 + o] = make_float2(v.x, v.x);
                dst[(k+1)*129 + o] = make_float2(v.y, v.y);
                dst[(k+2)*129 + o] = make_float2(v.z, v.z);
                dst[(k+3)*129 + o] = make_float2(v.w, v.w);
            }
        }
        __syncthreads();
        #pragma unroll 4
        for (int k = 0; k < 32; ++k) {
            ulonglong2 uv = myu[k0 + k];
            #pragma unroll
            for (int g = 0; g < 4; ++g) {
                ull d = stg[k*129 + lane + 32*g];
                o01[g] = ffma2(uv.x, d, o01[g]);
                o23[g] = ffma2(uv.y, d, o23[g]);
            }
        }
    }

    #pragma unroll
    for (int g = 0; g < 4; ++g) {
        float2 a = unpack2(o01[g]);
        float2 b = unpack2(o23[g]);
        out[(size_t)(r0+0)*OUTD + lane + 32*g] = a.x;
        out[(size_t)(r0+1)*OUTD + lane + 32*g] = a.y;
        out[(size_t)(r0+2)*OUTD + lane + 32*g] = b.x;
        out[(size_t)(r0+3)*OUTD + lane + 32*g] = b.y;
    }
}

extern "C" void kernel_launch(void* const* d_in, const int* in_sizes, int n_in,
                              void* d_out, int out_size)
{
    const float* u  = (const float*)d_in[0];  // [8192,128]
    const float* Bw = (const float*)d_in[1];  // [1024,128]
    const float* Bs = (const float*)d_in[2];  // [1024,1024]
    const float* Ds = (const float*)d_in[3];  // [128,1024]
    const float* Dw = (const float*)d_in[4];  // [128,128]

    cudaFuncSetAttribute(ren_kernel,
                         cudaFuncAttributeMaxDynamicSharedMemorySize, SMEM_BYTES);
    ren_kernel<<<BATCH / RPC, 256, SMEM_BYTES>>>(u, Bw, Bs, Ds, Dw, (float*)d_out);
}

// round 3
// speedup vs baseline: 1.3717x; 1.3717x over previous
#include <cuda_runtime.h>
#include <cstdint>

#define BATCH 8192
#define IND   128
#define HID   1024
#define OUTD  128
#define NW    8
#define RPW   4
#define RPC   (NW*RPW)     // 32 rows per CTA
#define TW    128          // column tile width
#define NTILE (HID/TW)     // 8
#define SLEN  (IND + HID)  // 1152: [u(128); s(1024)]
#define STGP  128          // stage pitch (floats per j-row)

// smem floats: sh = NW*SLEN*4 float-quads; stg = 2 x (32*128)
#define SH_FLOATS (NW*SLEN*4)
#define SMEM_FLOATS (SH_FLOATS + 2*32*STGP)
#define SMEM_BYTES  (SMEM_FLOATS * 4)

typedef unsigned long long ull;

__device__ __forceinline__ ull ffma2(ull a, ull b, ull c) {
    ull d; asm("fma.rn.f32x2 %0, %1, %2, %3;" : "=l"(d) : "l"(a), "l"(b), "l"(c));
    return d;
}
__device__ __forceinline__ ull dup2(float x) {
    ull d; asm("mov.b64 %0, {%1, %1};" : "=l"(d) : "f"(x)); return d;
}
__device__ __forceinline__ ull pack2(float x, float y) {
    ull d; asm("mov.b64 %0, {%1, %2};" : "=l"(d) : "f"(x), "f"(y)); return d;
}
__device__ __forceinline__ float2 unpack2(ull v) {
    float2 f; asm("mov.b64 {%0, %1}, %2;" : "=f"(f.x), "=f"(f.y) : "l"(v)); return f;
}
__device__ __forceinline__ float fast_tanh(float x) {
    // tanh(x) = 1 - 2/(exp(2x)+1), ex2.approx + rcp.approx (~1e-7 abs err)
    float e; asm("ex2.approx.f32 %0, %1;" : "=f"(e) : "f"(x * 2.8853900817779268f));
    float r; asm("rcp.approx.f32 %0, %1;" : "=f"(r) : "f"(e + 1.0f));
    return fmaf(-2.0f, r, 1.0f);
}

// stage a 32j x 128c chunk, transposed: buf[j*STGP + c] = src[c*ld + j]
__device__ __forceinline__ void stage_chunk(float* buf, const float* __restrict__ src,
                                            int ld, int tid) {
    const int c    = tid >> 1;
    const int part = tid & 1;            // 16 floats each
    const float4* s4 = (const float4*)(src + (size_t)c * ld + part * 16);
    #pragma unroll
    for (int i = 0; i < 4; ++i) {
        float4 v = s4[i];
        int j = part * 16 + i * 4;
        buf[(j+0)*STGP + c] = v.x;
        buf[(j+1)*STGP + c] = v.y;
        buf[(j+2)*STGP + c] = v.z;
        buf[(j+3)*STGP + c] = v.w;
    }
}

// dense 32-j update: acc[cols lane*4..+3] += s_j * b[j][col]
__device__ __forceinline__ void dense32(ull a01[4], ull a23[4],
                                        const ulonglong2* __restrict__ sbase,
                                        const float4* __restrict__ bbuf,
                                        int lane, bool active) {
    if (!active) return;
    #pragma unroll 8
    for (int j = 0; j < 32; ++j) {
        ulonglong2 sv = sbase[j];            // uniform broadcast: (r0,r1),(r2,r3)
        float4 b = bbuf[j*32 + lane];        // 4 cols for this lane
        ull b0 = dup2(b.x), b1 = dup2(b.y), b2 = dup2(b.z), b3 = dup2(b.w);
        a01[0] = ffma2(sv.x, b0, a01[0]);  a23[0] = ffma2(sv.y, b0, a23[0]);
        a01[1] = ffma2(sv.x, b1, a01[1]);  a23[1] = ffma2(sv.y, b1, a23[1]);
        a01[2] = ffma2(sv.x, b2, a01[2]);  a23[2] = ffma2(sv.y, b2, a23[2]);
        a01[3] = ffma2(sv.x, b3, a01[3]);  a23[3] = ffma2(sv.y, b3, a23[3]);
    }
}

// sequential 32-step sweep for diag sub-chunk cj (cols 32cj..32cj+31, lanes 8cj..8cj+7)
__device__ __forceinline__ void sweep32(ull a01[4], ull a23[4],
                                        const float4* __restrict__ bbuf,
                                        float4* __restrict__ sdst,
                                        int lane, int cj) {
    const int lbase = cj * 8;
    const int lloc  = lane - lbase;
    const bool act  = (lloc >= 0) && (lloc < 8);
    const int cl    = lloc * 4;          // local col base (garbage if !act)
    #pragma unroll
    for (int i = 0; i < 32; ++i) {
        const int q = i & 3;
        const int owner = lbase + (i >> 2);
        float2 p01 = unpack2(a01[q]);
        float2 p23 = unpack2(a23[q]);
        float t0 = fast_tanh(p01.x), t1 = fast_tanh(p01.y);
        float t2 = fast_tanh(p23.x), t3 = fast_tanh(p23.y);
        float v0 = __shfl_sync(0xffffffffu, t0, owner);
        float v1 = __shfl_sync(0xffffffffu, t1, owner);
        float v2 = __shfl_sync(0xffffffffu, t2, owner);
        float v3 = __shfl_sync(0xffffffffu, t3, owner);
        ull s01 = pack2(v0, v1);
        ull s23 = pack2(v2, v3);
        float4 b = bbuf[i*32 + lane];
        if (act) {
            if (cl + 0 > i) { ull bb = dup2(b.x); a01[0]=ffma2(s01,bb,a01[0]); a23[0]=ffma2(s23,bb,a23[0]); }
            if (cl + 1 > i) { ull bb = dup2(b.y); a01[1]=ffma2(s01,bb,a01[1]); a23[1]=ffma2(s23,bb,a23[1]); }
            if (cl + 2 > i) { ull bb = dup2(b.z); a01[2]=ffma2(s01,bb,a01[2]); a23[2]=ffma2(s23,bb,a23[2]); }
            if (cl + 3 > i) { ull bb = dup2(b.w); a01[3]=ffma2(s01,bb,a01[3]); a23[3]=ffma2(s23,bb,a23[3]); }
            if (lane == owner) sdst[i] = make_float4(t0, t1, t2, t3);
        }
    }
}

__global__ void __launch_bounds__(256, 1)
ren_kernel(const float* __restrict__ u,  const float* __restrict__ Bw,
           const float* __restrict__ Bs, const float* __restrict__ Ds,
           const float* __restrict__ Dw, float* __restrict__ out)
{
    extern __shared__ float smem[];
    float4* sh  = (float4*)smem;             // [NW][SLEN] float4 (4 batch rows)
    float*  stg = smem + SH_FLOATS;          // 2 x 4096 floats

    const int tid  = threadIdx.x;
    const int warp = tid >> 5;
    const int lane = tid & 31;
    const int r0   = blockIdx.x * RPC + warp * RPW;

    float4* mysh = sh + warp * SLEN;
    // prepend u rows: mysh[0..127] = u (4 rows interleaved)
    for (int k = lane; k < IND; k += 32)
        mysh[k] = make_float4(u[(size_t)(r0+0)*IND + k], u[(size_t)(r0+1)*IND + k],
                              u[(size_t)(r0+2)*IND + k], u[(size_t)(r0+3)*IND + k]);

    // ===== recurrence: 8 column-tiles of width 128 =====
    for (int t = 0; t < NTILE; ++t) {
        const int h0  = t * TW;
        const int nch = 8 + 4*t;     // 4 u-chunks + 4t history + 4 diag
        ull a01[4] = {0,0,0,0}, a23[4] = {0,0,0,0};

        stage_chunk(stg, Bw + (size_t)h0 * IND, IND, tid);  // chunk m=0
        __syncthreads();

        for (int m = 0; m < nch; ++m) {
            float* cur = stg + (m & 1) * (32*STGP);
            if (m + 1 < nch) {
                const int mm = m + 1;
                const float* src = (mm < 4) ? (Bw + (size_t)h0 * IND  + mm * 32)
                                            : (Bs + (size_t)h0 * HID + (size_t)(mm-4) * 32);
                stage_chunk(stg + ((m+1) & 1) * (32*STGP), src, (mm < 4) ? IND : HID, tid);
            }
            const ulonglong2* sbase = (const ulonglong2*)(mysh + 32 * m);  // jbase = 32m
            if (m < 4 + 4*t) {
                dense32(a01, a23, sbase, (const float4*)cur, lane, true);
            } else {
                const int cj = m - 4 - 4*t;
                sweep32(a01, a23, (const float4*)cur, mysh + IND + h0 + 32*cj, lane, cj);
                __syncwarp();
                dense32(a01, a23, sbase, (const float4*)cur, lane, lane >= 8*(cj+1));
            }
            __syncthreads();
        }
    }

    // ===== output: y = [u;s] @ [Dw|Ds]^T, 36 k-chunks =====
    {
        ull a01[4] = {0,0,0,0}, a23[4] = {0,0,0,0};
        stage_chunk(stg, Dw, IND, tid);
        __syncthreads();
        for (int m = 0; m < 36; ++m) {
            float* cur = stg + (m & 1) * (32*STGP);
            if (m + 1 < 36) {
                const int mm = m + 1;
                const float* src = (mm < 4) ? (Dw + mm * 32) : (Ds + (size_t)(mm-4) * 32);
                stage_chunk(stg + ((m+1) & 1) * (32*STGP), src, (mm < 4) ? IND : HID, tid);
            }
            dense32(a01, a23, (const ulonglong2*)(mysh + 32*m), (const float4*)cur, lane, true);
            __syncthreads();
        }

        float2 x01[4], x23[4];
        #pragma unroll
        for (int q = 0; q < 4; ++q) { x01[q] = unpack2(a01[q]); x23[q] = unpack2(a23[q]); }
        float4 v0 = make_float4(x01[0].x, x01[1].x, x01[2].x, x01[3].x);
        float4 v1 = make_float4(x01[0].y, x01[1].y, x01[2].y, x01[3].y);
        float4 v2 = make_float4(x23[0].x, x23[1].x, x23[2].x, x23[3].x);
        float4 v3 = make_float4(x23[0].y, x23[1].y, x23[2].y, x23[3].y);
        ((float4*)(out + (size_t)(r0+0)*OUTD))[lane] = v0;
        ((float4*)(out + (size_t)(r0+1)*OUTD))[lane] = v1;
        ((float4*)(out + (size_t)(r0+2)*OUTD))[lane] = v2;
        ((float4*)(out + (size_t)(r0+3)*OUTD))[lane] = v3;
    }
}

extern "C" void kernel_launch(void* const* d_in, const int* in_sizes, int n_in,
                              void* d_out, int out_size)
{
    const float* u  = (const float*)d_in[0];  // [8192,128]
    const float* Bw = (const float*)d_in[1];  // [1024,128]
    const float* Bs = (const float*)d_in[2];  // [1024,1024]
    const float* Ds = (const float*)d_in[3];  // [128,1024]
    const float* Dw = (const float*)d_in[4];  // [128,128]

    cudaFuncSetAttribute(ren_kernel,
                         cudaFuncAttributeMaxDynamicSharedMemorySize, SMEM_BYTES);
    ren_kernel<<<BATCH / RPC, 256, SMEM_BYTES>>>(u, Bw, Bs, Ds, Dw, (float*)d_out);
}